// round 2
// baseline (speedup 1.0000x reference)
#include <cuda_runtime.h>
#include <cstdint>

// ---------------- problem constants ----------------
#define M_DIM 512        // batch
#define K_DIM 512        // in_dim
#define N_DIM 100000     // out_dim (classes)
#define NC    10
#define CAND  16
#define SCALE 64.0f
#define COS_M  0.87758256189037276f   // cos(0.5)
#define SIN_M  0.47942553860420301f   // sin(0.5)
#define SINM_M 0.23971276930210150f   // sin(0.5)*0.5
#define EPSN  1e-12f
#define NEG_INF (-3.402823466e38f)

#define LOGITS_SZ ((size_t)M_DIM * N_DIM)          // 51,200,000
#define INTRA_OFF LOGITS_SZ                         // +512
#define HARD_OFF  (LOGITS_SZ + M_DIM)               // +5120

// ---------------- scratch (static device globals; no allocs) ----------------
__device__ float g_xn[M_DIM * K_DIM];   // row-normalized x
__device__ int   g_y[M_DIM];            // decoded labels (int32)
__device__ int   g_cand[M_DIM * CAND];  // top-16 candidate columns per row

// ---------------- packed f32x2 helpers (Blackwell FFMA2) ----------------
__device__ __forceinline__ unsigned long long pack2(float v) {
    unsigned long long r;
    asm("mov.b64 %0, {%1, %1};" : "=l"(r) : "f"(v));
    return r;
}
__device__ __forceinline__ void fma2(unsigned long long& d,
                                     unsigned long long a,
                                     unsigned long long b) {
    asm("fma.rn.f32x2 %0, %1, %2, %0;" : "+l"(d) : "l"(a), "l"(b));
}
__device__ __forceinline__ void unpack2(unsigned long long p, float& lo, float& hi) {
    asm("mov.b64 {%0, %1}, %2;" : "=f"(lo), "=f"(hi) : "l"(p));
}

// ---------------- kernel 0: decode y (int64 vs int32 auto-detect) -----------
__global__ void ydecode_kernel(const int* __restrict__ y32) {
    __shared__ int zeros;
    int t = threadIdx.x;                 // 512 threads
    if (t == 0) zeros = 0;
    __syncthreads();
    if (t < 256) {
        if (y32[2 * t + 1] == 0) atomicAdd(&zeros, 1);
    }
    __syncthreads();
    bool is64 = (zeros > 8);
    g_y[t] = is64 ? y32[2 * t] : y32[t];
}

// ---------------- kernel 1: row-normalize x ----------------
__global__ void xnorm_kernel(const float* __restrict__ x) {
    int gw   = (blockIdx.x * blockDim.x + threadIdx.x) >> 5;  // warp id = row
    int lane = threadIdx.x & 31;
    if (gw >= M_DIM) return;
    const float* xr = x + (size_t)gw * K_DIM;
    float v[16];
    float s = 0.f;
#pragma unroll
    for (int i = 0; i < 16; i++) {
        v[i] = xr[lane + 32 * i];
        s = fmaf(v[i], v[i], s);
    }
#pragma unroll
    for (int o = 16; o; o >>= 1) s += __shfl_xor_sync(0xffffffffu, s, o);
    float inv = 1.0f / fmaxf(sqrtf(s), EPSN);
#pragma unroll
    for (int i = 0; i < 16; i++)
        g_xn[(size_t)gw * K_DIM + lane + 32 * i] = v[i] * inv;
}

// ---------------- kernel 2: fused cosine GEMM + colnorm + margin epilogue ----
#define BM 128
#define BN 128
#define BK 16
#define APITCH 132   // padded A pitch (floats) to dodge STS bank conflicts

__global__ __launch_bounds__(256, 2)
void arcface_gemm_kernel(const float* __restrict__ W, float* __restrict__ out) {
    __shared__ float sA[BK * APITCH];          // A tile, transposed [k][m]
    __shared__ float sB[BK * BN];              // B tile [k][n]
    __shared__ float scs[256];                 // colsumsq partials
    __shared__ float colinv[BN];               // 1/||W_col||

    const int tid = threadIdx.x;
    const int m0  = blockIdx.x * BM;
    const int n0  = blockIdx.y * BN;
    const int tm  = tid >> 4;                  // 0..15
    const int tn  = tid & 15;                  // 0..15

    unsigned long long acc[8][4];
#pragma unroll
    for (int i = 0; i < 8; i++)
#pragma unroll
        for (int j = 0; j < 4; j++) acc[i][j] = 0ULL;

    float csum = 0.f;
    const int cs_c = tid & 127;     // column this thread accumulates sumsq for
    const int cs_k = tid >> 7;      // k parity

    float4 stA[2], stB[2];

    auto loadTiles = [&](int k0) {
#pragma unroll
        for (int u = 0; u < 2; u++) {
            int id = tid + u * 256;            // 0..511
            int r = id >> 2, f4 = id & 3;
            stA[u] = *reinterpret_cast<const float4*>(
                &g_xn[(size_t)(m0 + r) * K_DIM + k0 + f4 * 4]);
        }
#pragma unroll
        for (int u = 0; u < 2; u++) {
            int id = tid + u * 256;
            int kk = id >> 5, f4c = id & 31;
            int gc = n0 + f4c * 4;
            if (gc + 4 <= N_DIM)
                stB[u] = *reinterpret_cast<const float4*>(
                    &W[(size_t)(k0 + kk) * N_DIM + gc]);
            else
                stB[u] = make_float4(0.f, 0.f, 0.f, 0.f);
        }
    };
    auto storeTiles = [&]() {
#pragma unroll
        for (int u = 0; u < 2; u++) {
            int id = tid + u * 256;
            int r = id >> 2, f4 = id & 3;
            sA[(f4 * 4 + 0) * APITCH + r] = stA[u].x;
            sA[(f4 * 4 + 1) * APITCH + r] = stA[u].y;
            sA[(f4 * 4 + 2) * APITCH + r] = stA[u].z;
            sA[(f4 * 4 + 3) * APITCH + r] = stA[u].w;
        }
#pragma unroll
        for (int u = 0; u < 2; u++) {
            int id = tid + u * 256;
            int kk = id >> 5, f4c = id & 31;
            *reinterpret_cast<float4*>(&sB[kk * BN + f4c * 4]) = stB[u];
        }
    };

    loadTiles(0);
#pragma unroll 1
    for (int kc = 0; kc < K_DIM / BK; ++kc) {
        if (kc) __syncthreads();
        storeTiles();
        __syncthreads();
        if (kc + 1 < K_DIM / BK) loadTiles((kc + 1) * BK);

#pragma unroll
        for (int k = 0; k < BK; k++) {
            float4 a0 = *reinterpret_cast<const float4*>(&sA[k * APITCH + tm * 8]);
            float4 a1 = *reinterpret_cast<const float4*>(&sA[k * APITCH + tm * 8 + 4]);
            ulonglong2 q0 = *reinterpret_cast<const ulonglong2*>(&sB[k * BN + tn * 8]);
            ulonglong2 q1 = *reinterpret_cast<const ulonglong2*>(&sB[k * BN + tn * 8 + 4]);
            unsigned long long bp[4] = {q0.x, q0.y, q1.x, q1.y};
            float av[8] = {a0.x, a0.y, a0.z, a0.w, a1.x, a1.y, a1.z, a1.w};
#pragma unroll
            for (int i = 0; i < 8; i++) {
                unsigned long long ap = pack2(av[i]);
#pragma unroll
                for (int j = 0; j < 4; j++) fma2(acc[i][j], ap, bp[j]);
            }
        }
        // column sum-of-squares from the same smem tile (zero extra DRAM)
#pragma unroll
        for (int j = 0; j < 8; j++) {
            float v = sB[(cs_k + 2 * j) * BN + cs_c];
            csum = fmaf(v, v, csum);
        }
    }

    __syncthreads();
    scs[tid] = csum;
    __syncthreads();
    if (tid < 128) {
        float tot = scs[tid] + scs[tid + 128];
        colinv[tid] = 1.0f / fmaxf(sqrtf(tot), EPSN);
    }
    __syncthreads();

    // ---------------- epilogue ----------------
    float ci[8];
#pragma unroll
    for (int j = 0; j < 8; j++) ci[j] = colinv[tn * 8 + j];
    const bool fullcols = (n0 + tn * 8 + 8 <= N_DIM);

#pragma unroll
    for (int i = 0; i < 8; i++) {
        int row = m0 + tm * 8 + i;
        int yr = g_y[row];
        float res[8];
#pragma unroll
        for (int jp = 0; jp < 4; jp++) {
            float lo, hi;
            unpack2(acc[i][jp], lo, hi);
            res[2 * jp] = lo;
            res[2 * jp + 1] = hi;
        }
#pragma unroll
        for (int j = 0; j < 8; j++) {
            int col = n0 + tn * 8 + j;
            float c = res[j] * ci[j];
            c = fminf(1.f, fmaxf(-1.f, c));
            float lg = SCALE * c;
            if (col == yr) {
                float mg;
                if (c > -COS_M)
                    mg = c * COS_M - sqrtf(fmaxf(0.f, 1.f - c * c)) * SIN_M;
                else
                    mg = c - SINM_M;
                lg = SCALE * mg;
                out[INTRA_OFF + row] = c;      // intra_scores
            }
            res[j] = lg;
        }
        if (fullcols) {
            float* o = out + (size_t)row * N_DIM + n0 + tn * 8;
            *reinterpret_cast<float4*>(o)     = make_float4(res[0], res[1], res[2], res[3]);
            *reinterpret_cast<float4*>(o + 4) = make_float4(res[4], res[5], res[6], res[7]);
        }
    }
}

// ---------------- kernel 3: per-row top-16 candidate selection ----------------
// One block per row. Scale S is monotone so ranking logits == ranking cosine.
// Produces a superset (16) of the true top-10; exact ordering is resolved by
// the fp64 refine pass.
__global__ void topk_kernel(const float* __restrict__ logits) {
    const int row = blockIdx.x;
    const int t   = threadIdx.x;                // 512 threads
    const float* lr = logits + (size_t)row * N_DIM;
    const int yr = g_y[row];

    float v[CAND];
    int   id[CAND];
#pragma unroll
    for (int j = 0; j < CAND; j++) { v[j] = NEG_INF; id[j] = 0x7fffffff; }

    for (int c = t; c < N_DIM; c += 512) {
        float val = (c == yr) ? NEG_INF : lr[c];
        if (val > v[CAND - 1]) {
            v[CAND - 1] = val;
            id[CAND - 1] = c;
#pragma unroll
            for (int j = CAND - 1; j > 0; --j) {
                if (v[j] > v[j - 1]) {         // strict: keeps lower index first on ties
                    float tv = v[j]; v[j] = v[j - 1]; v[j - 1] = tv;
                    int ti = id[j]; id[j] = id[j - 1]; id[j - 1] = ti;
                }
            }
        }
    }

    __shared__ float sv[512];
    __shared__ int   si[512];
    int ptr = 0;
    for (int r = 0; r < CAND; ++r) {
        float myv = (ptr < CAND) ? v[ptr] : NEG_INF;
        int   myi = (ptr < CAND) ? id[ptr] : 0x7fffffff;
        sv[t] = myv;
        si[t] = myi;
        __syncthreads();
        for (int s = 256; s > 0; s >>= 1) {
            if (t < s) {
                float ov = sv[t + s];
                int   oi = si[t + s];
                if (ov > sv[t] || (ov == sv[t] && oi < si[t])) {
                    sv[t] = ov; si[t] = oi;
                }
            }
            __syncthreads();
        }
        if (ptr < CAND && sv[0] == myv && si[0] == myi) ptr++;   // my head won
        if (t == 0) g_cand[row * CAND + r] = si[0];
        __syncthreads();
    }
}

// ---------------- kernel 4: fp64 refine of the 16 candidates ----------------
// One block (512 threads = 16 warps) per row; warp w recomputes candidate w's
// cosine exactly in fp64, rounds to fp32 with the reference clip, then thread 0
// ranks the 16 (desc value, asc index on ties) and emits the top-10 indices.
__global__ void refine_kernel(const float* __restrict__ x,
                              const float* __restrict__ W,
                              float* __restrict__ out) {
    const int row  = blockIdx.x;
    const int t    = threadIdx.x;
    const int warp = t >> 5;
    const int lane = t & 31;

    const int c = g_cand[row * CAND + warp];

    double dot = 0.0, wss = 0.0, xss = 0.0;
    const float* xr = x + (size_t)row * K_DIM;
    for (int i = lane; i < K_DIM; i += 32) {
        double xi = (double)xr[i];
        double wi = (double)W[(size_t)i * N_DIM + c];
        dot = fma(xi, wi, dot);
        wss = fma(wi, wi, wss);
        xss = fma(xi, xi, xss);
    }
#pragma unroll
    for (int o = 16; o; o >>= 1) {
        dot += __shfl_xor_sync(0xffffffffu, dot, o);
        wss += __shfl_xor_sync(0xffffffffu, wss, o);
        xss += __shfl_xor_sync(0xffffffffu, xss, o);
    }

    __shared__ float cv[CAND];
    __shared__ int   ci[CAND];
    if (lane == 0) {
        double xn = sqrt(xss); if (xn < (double)EPSN) xn = (double)EPSN;
        double wn = sqrt(wss); if (wn < (double)EPSN) wn = (double)EPSN;
        float f = (float)(dot / (xn * wn));
        f = fminf(1.f, fmaxf(-1.f, f));   // reference clip, in fp32
        cv[warp] = f;
        ci[warp] = c;
    }
    __syncthreads();

    if (t == 0) {
        bool used[CAND];
#pragma unroll
        for (int j = 0; j < CAND; j++) used[j] = false;
        for (int r = 0; r < NC; ++r) {
            int   bj = -1;
            float bv = NEG_INF;
            int   bi = 0x7fffffff;
            for (int j = 0; j < CAND; ++j) {
                if (used[j]) continue;
                if (cv[j] > bv || (cv[j] == bv && ci[j] < bi)) {
                    bv = cv[j]; bi = ci[j]; bj = j;
                }
            }
            used[bj] = true;
            out[HARD_OFF + (size_t)row * NC + r] = (float)bi;
        }
    }
}

// ---------------- launch ----------------
extern "C" void kernel_launch(void* const* d_in, const int* in_sizes, int n_in,
                              void* d_out, int out_size) {
    const float* x  = (const float*)d_in[0];
    const float* W  = (const float*)d_in[1];
    const int*   y32 = (const int*)d_in[2];
    float* out = (float*)d_out;

    ydecode_kernel<<<1, 512>>>(y32);
    xnorm_kernel<<<(M_DIM * 32 + 255) / 256, 256>>>(x);
    dim3 grid(M_DIM / BM, (N_DIM + BN - 1) / BN);   // (4, 782): M fastest -> L2 reuse of W
    arcface_gemm_kernel<<<grid, 256>>>(W, out);
    topk_kernel<<<M_DIM, 512>>>(out);
    refine_kernel<<<M_DIM, 512>>>(x, W, out);
}

// round 4
// speedup vs baseline: 4.0195x; 4.0195x over previous
#include <cuda_runtime.h>
#include <cuda_fp16.h>
#include <cstdint>

// ---------------- problem constants ----------------
#define M_DIM 512
#define K_DIM 512
#define N_DIM 100000
#define NC    10
#define CAND  16
#define CAP   512
#define THR   0.125f
#define SCALE 64.0f
#define COS_M  0.87758256189037276f
#define SIN_M  0.47942553860420301f
#define SINM_M 0.23971276930210150f
#define EPSN  1e-12f
#define NEG_INF (-3.402823466e38f)

#define LOGITS_SZ ((size_t)M_DIM * N_DIM)
#define INTRA_OFF LOGITS_SZ
#define HARD_OFF  (LOGITS_SZ + M_DIM)

// ---------------- device scratch ----------------
__device__ __half g_xh[M_DIM * K_DIM];                    // normalized x, fp16
__device__ __half g_wh[(size_t)K_DIM * N_DIM + 128];      // W fp16 (+pad for edge cp.async)
__device__ float  g_colinv[N_DIM + 128];                  // 1/||W_col|| (+pad)
__device__ int    g_y[M_DIM];
__device__ int    g_cnt[M_DIM];
__device__ float  g_cval[M_DIM * CAP];
__device__ int    g_ccol[M_DIM * CAP];

// ---------------- PTX helpers (all plain sm_80+, no 'a' features) ----------
__device__ __forceinline__ uint32_t smem_u32(const void* p) {
    uint32_t a;
    asm("{ .reg .u64 t; cvta.to.shared.u64 t, %1; cvt.u32.u64 %0, t; }" : "=r"(a) : "l"(p));
    return a;
}
__device__ __forceinline__ void cpa16(uint32_t s, const void* g) {
    asm volatile("cp.async.cg.shared.global [%0], [%1], 16;" :: "r"(s), "l"(g));
}
#define CP_COMMIT() asm volatile("cp.async.commit_group;" ::: "memory")
#define CP_WAIT1()  asm volatile("cp.async.wait_group 1;" ::: "memory")

__device__ __forceinline__ void ldsm4(uint32_t* r, uint32_t a) {
    asm volatile("ldmatrix.sync.aligned.m8n8.x4.shared.b16 {%0,%1,%2,%3}, [%4];"
        : "=r"(r[0]), "=r"(r[1]), "=r"(r[2]), "=r"(r[3]) : "r"(a));
}
__device__ __forceinline__ void ldsm4t(uint32_t* r, uint32_t a) {
    asm volatile("ldmatrix.sync.aligned.m8n8.x4.trans.shared.b16 {%0,%1,%2,%3}, [%4];"
        : "=r"(r[0]), "=r"(r[1]), "=r"(r[2]), "=r"(r[3]) : "r"(a));
}
__device__ __forceinline__ void mma16816(float* c, const uint32_t* a, const uint32_t* b) {
    asm volatile("mma.sync.aligned.m16n8k16.row.col.f32.f16.f16.f32 "
        "{%0,%1,%2,%3}, {%4,%5,%6,%7}, {%8,%9}, {%0,%1,%2,%3};"
        : "+f"(c[0]), "+f"(c[1]), "+f"(c[2]), "+f"(c[3])
        : "r"(a[0]), "r"(a[1]), "r"(a[2]), "r"(a[3]), "r"(b[0]), "r"(b[1]));
}

// ---------------- kernel 0: decode y + zero counters + zero pads ----------
__global__ void ydecode_kernel(const int* __restrict__ y32) {
    __shared__ int zeros;
    int t = threadIdx.x;                 // 512
    if (t == 0) zeros = 0;
    __syncthreads();
    if (t < 256) {
        if (y32[2 * t + 1] == 0) atomicAdd(&zeros, 1);
    }
    __syncthreads();
    bool is64 = (zeros > 8);
    g_y[t] = is64 ? y32[2 * t] : y32[t];
    g_cnt[t] = 0;
    if (t < 128) {
        g_wh[(size_t)K_DIM * N_DIM + t] = __float2half(0.f);
        g_colinv[N_DIM + t] = 0.f;
    }
}

// ---------------- kernel 1: row-normalize x -> fp16 ----------------
__global__ void xnorm_kernel(const float* __restrict__ x) {
    int gw   = (blockIdx.x * blockDim.x + threadIdx.x) >> 5;
    int lane = threadIdx.x & 31;
    if (gw >= M_DIM) return;
    const float* xr = x + (size_t)gw * K_DIM;
    float v[16];
    float s = 0.f;
#pragma unroll
    for (int i = 0; i < 16; i++) {
        v[i] = xr[lane + 32 * i];
        s = fmaf(v[i], v[i], s);
    }
#pragma unroll
    for (int o = 16; o; o >>= 1) s += __shfl_xor_sync(0xffffffffu, s, o);
    float inv = 1.0f / fmaxf(sqrtf(s), EPSN);
#pragma unroll
    for (int i = 0; i < 16; i++)
        g_xh[(size_t)gw * K_DIM + lane + 32 * i] = __float2half(v[i] * inv);
}

// ---------------- kernel 2: W fp32 -> fp16 + column norms ----------------
// block = 128 columns, 256 threads (2 k-stripes per column)
__global__ void wconv_kernel(const float* __restrict__ W) {
    const int n0 = blockIdx.x * 128;
    const int t  = threadIdx.x;
    const int tn = t & 127, tk = t >> 7;
    const int n  = n0 + tn;
    float s = 0.f;
    if (n < N_DIM) {
#pragma unroll 8
        for (int k = tk; k < K_DIM; k += 2) {
            float v = W[(size_t)k * N_DIM + n];
            s = fmaf(v, v, s);
            g_wh[(size_t)k * N_DIM + n] = __float2half(v);
        }
    }
    __shared__ float sh[256];
    sh[t] = s;
    __syncthreads();
    if (t < 128 && n0 + t < N_DIM) {
        float tot = sh[t] + sh[t + 128];
        g_colinv[n0 + t] = 1.0f / fmaxf(sqrtf(tot), EPSN);
    }
}

// ---------------- kernel 3: fp16 mma.sync GEMM + fused epilogue ----------
// BM=128 BN=128 BK=64, 8 warps (2m x 4n), warp tile 64x32, double-buffered.
#define BK 64
#define STAGE_BYTES 32768          // A 16KB + B 16KB
#define SMEM_TOTAL  (2 * STAGE_BYTES)

__global__ __launch_bounds__(256, 2)
void arcface_gemm_kernel(float* __restrict__ out) {
    extern __shared__ char smem[];
    const uint32_t sb = smem_u32(smem);
    const int tid  = threadIdx.x;
    const int lane = tid & 31;
    const int w    = tid >> 5;
    const int wm   = w >> 2;              // 0..1
    const int wn   = w & 3;               // 0..3
    const int m0   = blockIdx.x * 128;
    const int n0   = blockIdx.y * 128;

    float acc[4][4][4];
#pragma unroll
    for (int a = 0; a < 4; a++)
#pragma unroll
        for (int b = 0; b < 4; b++)
#pragma unroll
            for (int c = 0; c < 4; c++) acc[a][b][c] = 0.f;

    // smem addressing with 16B-chunk XOR swizzle
    auto Aaddr = [&](int s, int m, int c) -> uint32_t {
        return sb + s * STAGE_BYTES + m * 128 + (((c ^ (m & 7)) & 7) << 4);
    };
    auto Baddr = [&](int s, int k, int c) -> uint32_t {
        return sb + s * STAGE_BYTES + 16384 + k * 256 + (((c ^ (k & 7)) & 15) << 4);
    };

    auto stage = [&](int s, int kc) {
        const int k0 = kc * BK;
#pragma unroll
        for (int j = 0; j < 4; j++) {              // A: 128m x 8 chunks
            int l = tid + j * 256;
            int m = l >> 3, c = l & 7;
            cpa16(Aaddr(s, m, c), g_xh + (size_t)(m0 + m) * K_DIM + k0 + c * 8);
        }
#pragma unroll
        for (int j = 0; j < 4; j++) {              // B: 64k x 16 chunks
            int l = tid + j * 256;
            int k = l >> 4, c = l & 15;
            cpa16(Baddr(s, k, c), g_wh + (size_t)(k0 + k) * N_DIM + n0 + c * 8);
        }
    };

    const int g  = lane >> 3;       // ldmatrix sub-matrix group
    const int l8 = lane & 7;

    auto compute = [&](int s) {
#pragma unroll
        for (int kk = 0; kk < 4; kk++) {
            uint32_t af[4][4];
#pragma unroll
            for (int mi = 0; mi < 4; mi++) {
                int ml = wm * 64 + mi * 16 + (g & 1) * 8 + l8;
                int c0 = kk * 2 + (g >> 1);
                ldsm4(af[mi], Aaddr(s, ml, c0));
            }
            uint32_t bf[2][4];
#pragma unroll
            for (int np = 0; np < 2; np++) {
                int kl = kk * 16 + (g & 1) * 8 + l8;
                int cn = wn * 4 + np * 2 + (g >> 1);
                ldsm4t(bf[np], Baddr(s, kl, cn));
            }
#pragma unroll
            for (int mi = 0; mi < 4; mi++)
#pragma unroll
                for (int ni = 0; ni < 4; ni++)
                    mma16816(acc[mi][ni], af[mi], &bf[ni >> 1][(ni & 1) * 2]);
        }
    };

    stage(0, 0); CP_COMMIT();
    stage(1, 1); CP_COMMIT();
#pragma unroll 1
    for (int kc = 0; kc < 8; kc++) {
        CP_WAIT1();
        __syncthreads();
        compute(kc & 1);
        __syncthreads();
        if (kc + 2 < 8) stage(kc & 1, kc + 2);
        CP_COMMIT();
    }

    // ---------------- epilogue ----------------
    const bool fullt = (n0 + 128 <= N_DIM);
#pragma unroll
    for (int mi = 0; mi < 4; mi++) {
        const int rbase = m0 + wm * 64 + mi * 16 + (lane >> 2);
#pragma unroll
        for (int h = 0; h < 2; h++) {
            const int row = rbase + h * 8;
            const int yr  = g_y[row];
            float* orow = out + (size_t)row * N_DIM;
#pragma unroll
            for (int ni = 0; ni < 4; ni++) {
                const int cb = n0 + wn * 32 + ni * 8 + (lane & 3) * 2;
                float lg[2];
#pragma unroll
                for (int e = 0; e < 2; e++) {
                    const int col = cb + e;
                    float c = acc[mi][ni][h * 2 + e] * __ldg(&g_colinv[col]);
                    c = fminf(1.f, fmaxf(-1.f, c));
                    float l = SCALE * c;
                    if (col == yr) {
                        float mg;
                        if (c > -COS_M)
                            mg = c * COS_M - sqrtf(fmaxf(0.f, 1.f - c * c)) * SIN_M;
                        else
                            mg = c - SINM_M;
                        l = SCALE * mg;
                        out[INTRA_OFF + row] = c;
                    } else if (c > THR && col < N_DIM) {
                        int slot = atomicAdd(&g_cnt[row], 1);
                        if (slot < CAP) {
                            g_cval[row * CAP + slot] = c;
                            g_ccol[row * CAP + slot] = col;
                        }
                    }
                    lg[e] = l;
                }
                if (fullt) {
                    *reinterpret_cast<float2*>(orow + cb) = make_float2(lg[0], lg[1]);
                } else {
                    if (cb     < N_DIM) orow[cb]     = lg[0];
                    if (cb + 1 < N_DIM) orow[cb + 1] = lg[1];
                }
            }
        }
    }
}

// ---------------- kernel 4: candidate select + fp64 refine ----------------
__global__ void refine_kernel(const float* __restrict__ x,
                              const float* __restrict__ W,
                              float* __restrict__ out) {
    const int row  = blockIdx.x;
    const int t    = threadIdx.x;
    const int warp = t >> 5;
    const int lane = t & 31;
    const int yr   = g_y[row];

    __shared__ float sv[512];
    __shared__ int   si[512];
    __shared__ int   list[CAND];

    const int cnt = g_cnt[row];
    if (cnt >= CAND && cnt <= CAP) {
        float myv = (t < cnt) ? g_cval[row * CAP + t] : NEG_INF;
        int   myi = (t < cnt) ? g_ccol[row * CAP + t] : 0x7fffffff;
        for (int r = 0; r < CAND; ++r) {
            sv[t] = myv;
            si[t] = myi;
            __syncthreads();
            for (int s = 256; s > 0; s >>= 1) {
                if (t < s) {
                    float ov = sv[t + s];
                    int   oi = si[t + s];
                    if (ov > sv[t] || (ov == sv[t] && oi < si[t])) {
                        sv[t] = ov; si[t] = oi;
                    }
                }
                __syncthreads();
            }
            if (t == 0) list[r] = si[0];
            if (myi == si[0]) myv = NEG_INF;       // unique cols -> unique winner
            __syncthreads();
        }
    } else {
        // fallback: full scan of this row's logits (monotone in cosine)
        const float* lr = out + (size_t)row * N_DIM;
        float v[CAND];
        int   id[CAND];
#pragma unroll
        for (int j = 0; j < CAND; j++) { v[j] = NEG_INF; id[j] = 0x7fffffff; }
        for (int c = t; c < N_DIM; c += 512) {
            float val = (c == yr) ? NEG_INF : lr[c];
            if (val > v[CAND - 1]) {
                v[CAND - 1] = val;
                id[CAND - 1] = c;
#pragma unroll
                for (int j = CAND - 1; j > 0; --j) {
                    if (v[j] > v[j - 1]) {
                        float tv = v[j]; v[j] = v[j - 1]; v[j - 1] = tv;
                        int ti = id[j]; id[j] = id[j - 1]; id[j - 1] = ti;
                    }
                }
            }
        }
        int ptr = 0;
        for (int r = 0; r < CAND; ++r) {
            float myv = (ptr < CAND) ? v[ptr] : NEG_INF;
            int   myi = (ptr < CAND) ? id[ptr] : 0x7fffffff;
            sv[t] = myv;
            si[t] = myi;
            __syncthreads();
            for (int s = 256; s > 0; s >>= 1) {
                if (t < s) {
                    float ov = sv[t + s];
                    int   oi = si[t + s];
                    if (ov > sv[t] || (ov == sv[t] && oi < si[t])) {
                        sv[t] = ov; si[t] = oi;
                    }
                }
                __syncthreads();
            }
            if (ptr < CAND && sv[0] == myv && si[0] == myi) ptr++;
            if (t == 0) list[r] = si[0];
            __syncthreads();
        }
    }
    __syncthreads();

    // fp64 exact recompute of the 16 candidates (warp per candidate)
    const int c = list[warp];
    double dot = 0.0, wss = 0.0, xss = 0.0;
    const float* xr = x + (size_t)row * K_DIM;
    for (int i = lane; i < K_DIM; i += 32) {
        double xi = (double)xr[i];
        double wi = (double)W[(size_t)i * N_DIM + c];
        dot = fma(xi, wi, dot);
        wss = fma(wi, wi, wss);
        xss = fma(xi, xi, xss);
    }
#pragma unroll
    for (int o = 16; o; o >>= 1) {
        dot += __shfl_xor_sync(0xffffffffu, dot, o);
        wss += __shfl_xor_sync(0xffffffffu, wss, o);
        xss += __shfl_xor_sync(0xffffffffu, xss, o);
    }

    __shared__ float cv[CAND];
    __shared__ int   ci[CAND];
    if (lane == 0) {
        double xn = sqrt(xss); if (xn < (double)EPSN) xn = (double)EPSN;
        double wn = sqrt(wss); if (wn < (double)EPSN) wn = (double)EPSN;
        float f = (float)(dot / (xn * wn));
        f = fminf(1.f, fmaxf(-1.f, f));
        cv[warp] = f;
        ci[warp] = c;
    }
    __syncthreads();

    if (t == 0) {
        bool used[CAND];
#pragma unroll
        for (int j = 0; j < CAND; j++) used[j] = false;
        for (int r = 0; r < NC; ++r) {
            int   bj = -1;
            float bv = NEG_INF;
            int   bi = 0x7fffffff;
            for (int j = 0; j < CAND; ++j) {
                if (used[j]) continue;
                if (cv[j] > bv || (cv[j] == bv && ci[j] < bi)) {
                    bv = cv[j]; bi = ci[j]; bj = j;
                }
            }
            used[bj] = true;
            out[HARD_OFF + (size_t)row * NC + r] = (float)bi;
        }
    }
}

// ---------------- launch ----------------
extern "C" void kernel_launch(void* const* d_in, const int* in_sizes, int n_in,
                              void* d_out, int out_size) {
    const float* x   = (const float*)d_in[0];
    const float* W   = (const float*)d_in[1];
    const int*   y32 = (const int*)d_in[2];
    float* out = (float*)d_out;

    cudaFuncSetAttribute(arcface_gemm_kernel,
                         cudaFuncAttributeMaxDynamicSharedMemorySize, SMEM_TOTAL);

    ydecode_kernel<<<1, 512>>>(y32);
    xnorm_kernel<<<64, 256>>>(x);
    wconv_kernel<<<(N_DIM + 127) / 128, 256>>>(W);
    dim3 grid(4, (N_DIM + 127) / 128);   // M fastest -> W L2 reuse across M-tiles
    arcface_gemm_kernel<<<grid, 256, SMEM_TOTAL>>>(out);
    refine_kernel<<<M_DIM, 512>>>(x, W, out);
}

// round 6
// speedup vs baseline: 4.8279x; 1.2011x over previous
#include <cuda_runtime.h>
#include <cuda_fp16.h>
#include <cstdint>

// ---------------- problem constants ----------------
#define M_DIM 512
#define K_DIM 512
#define N_DIM 100000
#define NC    10
#define CAND  16
#define CAP   512
#define THR   0.125f
#define SCALE 64.0f
#define COS_M  0.87758256189037276f
#define SIN_M  0.47942553860420301f
#define SINM_M 0.23971276930210150f
#define EPSN  1e-12f
#define NEG_INF (-3.402823466e38f)

#define LOGITS_SZ ((size_t)M_DIM * N_DIM)
#define INTRA_OFF LOGITS_SZ
#define HARD_OFF  (LOGITS_SZ + M_DIM)

// ---------------- device scratch ----------------
__device__ __half g_xh[M_DIM * K_DIM];
__device__ __half g_wh[(size_t)K_DIM * N_DIM + 128];
__device__ float  g_colinv[N_DIM + 128];
__device__ int    g_y[M_DIM];
__device__ int    g_cnt[M_DIM];
__device__ float  g_cval[M_DIM * CAP];
__device__ int    g_ccol[M_DIM * CAP];

// ---------------- PTX helpers ----------------
__device__ __forceinline__ uint32_t smem_u32(const void* p) {
    uint32_t a;
    asm("{ .reg .u64 t; cvta.to.shared.u64 t, %1; cvt.u32.u64 %0, t; }" : "=r"(a) : "l"(p));
    return a;
}
__device__ __forceinline__ void cpa16(uint32_t s, const void* g) {
    asm volatile("cp.async.cg.shared.global [%0], [%1], 16;" :: "r"(s), "l"(g));
}
#define CP_COMMIT() asm volatile("cp.async.commit_group;" ::: "memory")
#define CP_WAIT1()  asm volatile("cp.async.wait_group 1;" ::: "memory")

__device__ __forceinline__ void ldsm4(uint32_t* r, uint32_t a) {
    asm volatile("ldmatrix.sync.aligned.m8n8.x4.shared.b16 {%0,%1,%2,%3}, [%4];"
        : "=r"(r[0]), "=r"(r[1]), "=r"(r[2]), "=r"(r[3]) : "r"(a));
}
__device__ __forceinline__ void ldsm4t(uint32_t* r, uint32_t a) {
    asm volatile("ldmatrix.sync.aligned.m8n8.x4.trans.shared.b16 {%0,%1,%2,%3}, [%4];"
        : "=r"(r[0]), "=r"(r[1]), "=r"(r[2]), "=r"(r[3]) : "r"(a));
}
__device__ __forceinline__ void mma16816(float* c, const uint32_t* a, const uint32_t* b) {
    asm volatile("mma.sync.aligned.m16n8k16.row.col.f32.f16.f16.f32 "
        "{%0,%1,%2,%3}, {%4,%5,%6,%7}, {%8,%9}, {%0,%1,%2,%3};"
        : "+f"(c[0]), "+f"(c[1]), "+f"(c[2]), "+f"(c[3])
        : "r"(a[0]), "r"(a[1]), "r"(a[2]), "r"(a[3]), "r"(b[0]), "r"(b[1]));
}

// ---- double-single (compensated fp32) accumulation ----
struct DS { float hi, lo; };
__device__ __forceinline__ void ds_add(DS& a, float p) {
    float s = a.hi + p;
    float v = s - a.hi;
    float e = (a.hi - (s - v)) + (p - v);
    a.hi = s;
    a.lo += e;
}
__device__ __forceinline__ void ds_fma(DS& a, float x, float w) {
    float p  = x * w;
    float pe = fmaf(x, w, -p);       // exact product error
    ds_add(a, p);
    a.lo += pe;
}
__device__ __forceinline__ void ds_reduce(DS& a) {
#pragma unroll
    for (int o = 16; o; o >>= 1) {
        float oh = __shfl_xor_sync(0xffffffffu, a.hi, o);
        float ol = __shfl_xor_sync(0xffffffffu, a.lo, o);
        float s = a.hi + oh;
        float v = s - a.hi;
        float e = (a.hi - (s - v)) + (oh - v);
        a.hi = s;
        a.lo += ol + e;
    }
}

// ---------------- kernel 0: decode y + zero counters + zero pads ----------
__global__ void ydecode_kernel(const int* __restrict__ y32) {
    __shared__ int zeros;
    int t = threadIdx.x;
    if (t == 0) zeros = 0;
    __syncthreads();
    if (t < 256) {
        if (y32[2 * t + 1] == 0) atomicAdd(&zeros, 1);
    }
    __syncthreads();
    bool is64 = (zeros > 8);
    g_y[t] = is64 ? y32[2 * t] : y32[t];
    g_cnt[t] = 0;
    if (t < 128) {
        g_wh[(size_t)K_DIM * N_DIM + t] = __float2half(0.f);
        g_colinv[N_DIM + t] = 0.f;
    }
}

// ---------------- kernel 1: row-normalize x -> fp16 ----------------
__global__ void xnorm_kernel(const float* __restrict__ x) {
    int gw   = (blockIdx.x * blockDim.x + threadIdx.x) >> 5;
    int lane = threadIdx.x & 31;
    if (gw >= M_DIM) return;
    const float* xr = x + (size_t)gw * K_DIM;
    float v[16];
    float s = 0.f;
#pragma unroll
    for (int i = 0; i < 16; i++) {
        v[i] = xr[lane + 32 * i];
        s = fmaf(v[i], v[i], s);
    }
#pragma unroll
    for (int o = 16; o; o >>= 1) s += __shfl_xor_sync(0xffffffffu, s, o);
    float inv = 1.0f / fmaxf(sqrtf(s), EPSN);
#pragma unroll
    for (int i = 0; i < 16; i++)
        g_xh[(size_t)gw * K_DIM + lane + 32 * i] = __float2half(v[i] * inv);
}

// ---------------- kernel 2: W fp32 -> fp16 + column norms ----------------
__global__ void wconv_kernel(const float* __restrict__ W) {
    const int n0 = blockIdx.x * 128;
    const int t  = threadIdx.x;
    const int tn = t & 127, tk = t >> 7;
    const int n  = n0 + tn;
    float s = 0.f;
    if (n < N_DIM) {
#pragma unroll 8
        for (int k = tk; k < K_DIM; k += 2) {
            float v = W[(size_t)k * N_DIM + n];
            s = fmaf(v, v, s);
            g_wh[(size_t)k * N_DIM + n] = __float2half(v);
        }
    }
    __shared__ float sh[256];
    sh[t] = s;
    __syncthreads();
    if (t < 128 && n0 + t < N_DIM) {
        float tot = sh[t] + sh[t + 128];
        g_colinv[n0 + t] = 1.0f / fmaxf(sqrtf(tot), EPSN);
    }
}

// ---------------- kernel 3: fp16 mma.sync GEMM (3-stage) + fused epilogue --
#define BK 64
#define STAGE_BYTES 32768
#define SMEM_TOTAL  (3 * STAGE_BYTES)

__global__ __launch_bounds__(256, 2)
void arcface_gemm_kernel(float* __restrict__ out) {
    extern __shared__ char smem[];
    const uint32_t sb = smem_u32(smem);
    const int tid  = threadIdx.x;
    const int lane = tid & 31;
    const int w    = tid >> 5;
    const int wm   = w >> 2;
    const int wn   = w & 3;
    const int m0   = blockIdx.x * 128;
    const int n0   = blockIdx.y * 128;

    float acc[4][4][4];
#pragma unroll
    for (int a = 0; a < 4; a++)
#pragma unroll
        for (int b = 0; b < 4; b++)
#pragma unroll
            for (int c = 0; c < 4; c++) acc[a][b][c] = 0.f;

    auto Aaddr = [&](int s, int m, int c) -> uint32_t {
        return sb + s * STAGE_BYTES + m * 128 + (((c ^ (m & 7)) & 7) << 4);
    };
    auto Baddr = [&](int s, int k, int c) -> uint32_t {
        return sb + s * STAGE_BYTES + 16384 + k * 256 + (((c ^ (k & 7)) & 15) << 4);
    };

    auto stage = [&](int s, int kc) {
        const int k0 = kc * BK;
#pragma unroll
        for (int j = 0; j < 4; j++) {
            int l = tid + j * 256;
            int m = l >> 3, c = l & 7;
            cpa16(Aaddr(s, m, c), g_xh + (size_t)(m0 + m) * K_DIM + k0 + c * 8);
        }
#pragma unroll
        for (int j = 0; j < 4; j++) {
            int l = tid + j * 256;
            int k = l >> 4, c = l & 15;
            cpa16(Baddr(s, k, c), g_wh + (size_t)(k0 + k) * N_DIM + n0 + c * 8);
        }
    };

    const int g  = lane >> 3;
    const int l8 = lane & 7;

    auto compute = [&](int s) {
#pragma unroll
        for (int kk = 0; kk < 4; kk++) {
            uint32_t af[4][4];
#pragma unroll
            for (int mi = 0; mi < 4; mi++) {
                int ml = wm * 64 + mi * 16 + (g & 1) * 8 + l8;
                int c0 = kk * 2 + (g >> 1);
                ldsm4(af[mi], Aaddr(s, ml, c0));
            }
            uint32_t bf[2][4];
#pragma unroll
            for (int np = 0; np < 2; np++) {
                int kl = kk * 16 + (g & 1) * 8 + l8;
                int cn = wn * 4 + np * 2 + (g >> 1);
                ldsm4t(bf[np], Baddr(s, kl, cn));
            }
#pragma unroll
            for (int mi = 0; mi < 4; mi++)
#pragma unroll
                for (int ni = 0; ni < 4; ni++)
                    mma16816(acc[mi][ni], af[mi], &bf[ni >> 1][(ni & 1) * 2]);
        }
    };

    stage(0, 0); CP_COMMIT();
    stage(1, 1); CP_COMMIT();
#pragma unroll 1
    for (int kc = 0; kc < 8; kc++) {
        CP_WAIT1();
        __syncthreads();             // buffer kc%3 visible; buffer (kc+2)%3 retired
        if (kc + 2 < 8) stage((kc + 2) % 3, kc + 2);
        CP_COMMIT();
        compute(kc % 3);
    }

    // ---------------- epilogue ----------------
    const bool fullt = (n0 + 128 <= N_DIM);
#pragma unroll
    for (int mi = 0; mi < 4; mi++) {
        const int rbase = m0 + wm * 64 + mi * 16 + (lane >> 2);
#pragma unroll
        for (int h = 0; h < 2; h++) {
            const int row = rbase + h * 8;
            const int yr  = g_y[row];
            float* orow = out + (size_t)row * N_DIM;
#pragma unroll
            for (int ni = 0; ni < 4; ni++) {
                const int cb = n0 + wn * 32 + ni * 8 + (lane & 3) * 2;
                float lg[2];
#pragma unroll
                for (int e = 0; e < 2; e++) {
                    const int col = cb + e;
                    float c = acc[mi][ni][h * 2 + e] * __ldg(&g_colinv[col]);
                    c = fminf(1.f, fmaxf(-1.f, c));
                    float l = SCALE * c;
                    if (col == yr) {
                        float mg;
                        if (c > -COS_M)
                            mg = c * COS_M - sqrtf(fmaxf(0.f, 1.f - c * c)) * SIN_M;
                        else
                            mg = c - SINM_M;
                        l = SCALE * mg;
                        out[INTRA_OFF + row] = c;
                    } else if (c > THR && col < N_DIM) {
                        int slot = atomicAdd(&g_cnt[row], 1);
                        if (slot < CAP) {
                            g_cval[row * CAP + slot] = c;
                            g_ccol[row * CAP + slot] = col;
                        }
                    }
                    lg[e] = l;
                }
                if (fullt) {
                    *reinterpret_cast<float2*>(orow + cb) = make_float2(lg[0], lg[1]);
                } else {
                    if (cb     < N_DIM) orow[cb]     = lg[0];
                    if (cb + 1 < N_DIM) orow[cb + 1] = lg[1];
                }
            }
        }
    }
}

// ---------------- kernel 4: candidate select + double-single refine --------
__global__ void refine_kernel(const float* __restrict__ x,
                              const float* __restrict__ W,
                              float* __restrict__ out) {
    const int row  = blockIdx.x;
    const int t    = threadIdx.x;
    const int warp = t >> 5;
    const int lane = t & 31;
    const int yr   = g_y[row];

    __shared__ int list[CAND];
    const int cnt = g_cnt[row];

    if (cnt >= CAND && cnt <= CAP) {
        // single-warp top-16 select: register heaps + shfl argmax, no barriers
        if (warp == 0) {
            float v[CAND];
            int   id[CAND];
#pragma unroll
            for (int j = 0; j < CAND; j++) { v[j] = NEG_INF; id[j] = 0x7fffffff; }
            for (int i = lane; i < cnt; i += 32) {
                float val = g_cval[row * CAP + i];
                int   col = g_ccol[row * CAP + i];
                if (val > v[CAND - 1]) {
                    v[CAND - 1] = val;
                    id[CAND - 1] = col;
#pragma unroll
                    for (int j = CAND - 1; j > 0; --j) {
                        if (v[j] > v[j - 1]) {
                            float tv = v[j]; v[j] = v[j - 1]; v[j - 1] = tv;
                            int ti = id[j]; id[j] = id[j - 1]; id[j - 1] = ti;
                        }
                    }
                }
            }
            int ptr = 0;
            for (int r = 0; r < CAND; ++r) {
                float myv = (ptr < CAND) ? v[ptr] : NEG_INF;
                int   myi = (ptr < CAND) ? id[ptr] : 0x7fffffff;
                float bv = myv;
                int   bi = myi;
#pragma unroll
                for (int o = 16; o; o >>= 1) {
                    float ov = __shfl_xor_sync(0xffffffffu, bv, o);
                    int   oi = __shfl_xor_sync(0xffffffffu, bi, o);
                    if (ov > bv || (ov == bv && oi < bi)) { bv = ov; bi = oi; }
                }
                if (ptr < CAND && bi == myi) ptr++;    // unique cols -> unique winner
                if (lane == 0) list[r] = bi;
            }
        }
        __syncthreads();
    } else {
        // fallback: block-wide full scan of this row's logits
        __shared__ float sv[512];
        __shared__ int   si[512];
        const float* lr = out + (size_t)row * N_DIM;
        float v[CAND];
        int   id[CAND];
#pragma unroll
        for (int j = 0; j < CAND; j++) { v[j] = NEG_INF; id[j] = 0x7fffffff; }
        for (int c = t; c < N_DIM; c += 512) {
            float val = (c == yr) ? NEG_INF : lr[c];
            if (val > v[CAND - 1]) {
                v[CAND - 1] = val;
                id[CAND - 1] = c;
#pragma unroll
                for (int j = CAND - 1; j > 0; --j) {
                    if (v[j] > v[j - 1]) {
                        float tv = v[j]; v[j] = v[j - 1]; v[j - 1] = tv;
                        int ti = id[j]; id[j] = id[j - 1]; id[j - 1] = ti;
                    }
                }
            }
        }
        int ptr = 0;
        for (int r = 0; r < CAND; ++r) {
            float myv = (ptr < CAND) ? v[ptr] : NEG_INF;
            int   myi = (ptr < CAND) ? id[ptr] : 0x7fffffff;
            sv[t] = myv;
            si[t] = myi;
            __syncthreads();
            for (int s = 256; s > 0; s >>= 1) {
                if (t < s) {
                    float ov = sv[t + s];
                    int   oi = si[t + s];
                    if (ov > sv[t] || (ov == sv[t] && oi < si[t])) {
                        sv[t] = ov; si[t] = oi;
                    }
                }
                __syncthreads();
            }
            if (ptr < CAND && sv[0] == myv && si[0] == myi) ptr++;
            if (t == 0) list[r] = si[0];
            __syncthreads();
        }
    }

    // ---- double-single exact recompute of the 16 candidates ----
    const int c = list[warp];
    DS dot = {0.f, 0.f}, wss = {0.f, 0.f}, xss = {0.f, 0.f};
    const float* xr = x + (size_t)row * K_DIM;
#pragma unroll 4
    for (int i = lane; i < K_DIM; i += 32) {
        float xi = xr[i];
        float wi = W[(size_t)i * N_DIM + c];
        ds_fma(dot, xi, wi);
        ds_fma(wss, wi, wi);
        ds_fma(xss, xi, xi);
    }
    ds_reduce(dot);
    ds_reduce(wss);
    ds_reduce(xss);

    __shared__ float cv[CAND];
    __shared__ int   ci[CAND];
    if (lane == 0) {
        double dd = (double)dot.hi + (double)dot.lo;
        double dw = (double)wss.hi + (double)wss.lo;
        double dx = (double)xss.hi + (double)xss.lo;
        double xn = sqrt(dx); if (xn < (double)EPSN) xn = (double)EPSN;
        double wn = sqrt(dw); if (wn < (double)EPSN) wn = (double)EPSN;
        float f = (float)(dd / (xn * wn));
        f = fminf(1.f, fmaxf(-1.f, f));
        cv[warp] = f;
        ci[warp] = c;
    }
    __syncthreads();

    if (t == 0) {
        bool used[CAND];
#pragma unroll
        for (int j = 0; j < CAND; j++) used[j] = false;
        for (int r = 0; r < NC; ++r) {
            int   bj = -1;
            float bv = NEG_INF;
            int   bi = 0x7fffffff;
            for (int j = 0; j < CAND; ++j) {
                if (used[j]) continue;
                if (cv[j] > bv || (cv[j] == bv && ci[j] < bi)) {
                    bv = cv[j]; bi = ci[j]; bj = j;
                }
            }
            used[bj] = true;
            out[HARD_OFF + (size_t)row * NC + r] = (float)bi;
        }
    }
}

// ---------------- launch ----------------
extern "C" void kernel_launch(void* const* d_in, const int* in_sizes, int n_in,
                              void* d_out, int out_size) {
    const float* x   = (const float*)d_in[0];
    const float* W   = (const float*)d_in[1];
    const int*   y32 = (const int*)d_in[2];
    float* out = (float*)d_out;

    cudaFuncSetAttribute(arcface_gemm_kernel,
                         cudaFuncAttributeMaxDynamicSharedMemorySize, SMEM_TOTAL);

    ydecode_kernel<<<1, 512>>>(y32);
    xnorm_kernel<<<64, 256>>>(x);
    wconv_kernel<<<(N_DIM + 127) / 128, 256>>>(W);
    dim3 grid(4, (N_DIM + 127) / 128);
    arcface_gemm_kernel<<<grid, 256, SMEM_TOTAL>>>(out);
    refine_kernel<<<M_DIM, 512>>>(x, W, out);
}